// round 7
// baseline (speedup 1.0000x reference)
#include <cuda_runtime.h>
#include <math.h>

#define NG   256
#define HGT  512
#define WID  512
#define HW   (HGT * WID)
#define TB   128
#define GTH  64                // threads per gabor-half
#define PPB  128               // pixels per block (2 per pixel-thread)
#define NBLK (HW / PPB)        // 2048

// ---- constants -------------------------------------------------------------
constexpr double TWOPI_D  = 6.283185307179586476925286766559;
constexpr float  TWOPI_F  = (float)TWOPI_D;
constexpr float  RC1      = (float)TWOPI_D;
constexpr float  RC2      = (float)(TWOPI_D - (double)RC1);
constexpr float  INV2PI_F = (float)(1.0 / TWOPI_D);
constexpr double INV2PI_D = 1.0 / TWOPI_D;
constexpr float  L2E_F    = 1.4426950408889634f;   // == __expf's log2(e)
constexpr float  MAGIC_F  = 12582912.0f;           // 2^23 + 2^22: rne rounder

// ---- packed f32x2 helpers (each half bitwise identical to scalar op) --------
typedef unsigned long long F2;

__device__ __forceinline__ F2 f2pack(float lo, float hi) {
    F2 r; asm("mov.b64 %0, {%1, %2};" : "=l"(r) : "f"(lo), "f"(hi)); return r;
}
__device__ __forceinline__ void f2unpack(F2 v, float& lo, float& hi) {
    asm("mov.b64 {%0, %1}, %2;" : "=f"(lo), "=f"(hi) : "l"(v));
}
__device__ __forceinline__ F2 f2add(F2 a, F2 b) {
    F2 r; asm("add.rn.f32x2 %0, %1, %2;" : "=l"(r) : "l"(a), "l"(b)); return r;
}
__device__ __forceinline__ F2 f2sub(F2 a, F2 b) {
    F2 r; asm("sub.rn.f32x2 %0, %1, %2;" : "=l"(r) : "l"(a), "l"(b)); return r;
}
__device__ __forceinline__ F2 f2mul(F2 a, F2 b) {
    F2 r; asm("mul.rn.f32x2 %0, %1, %2;" : "=l"(r) : "l"(a), "l"(b)); return r;
}
__device__ __forceinline__ F2 f2fma(F2 a, F2 b, F2 c) {
    F2 r; asm("fma.rn.f32x2 %0, %1, %2, %3;" : "=l"(r) : "l"(a), "l"(b), "l"(c)); return r;
}
__device__ __forceinline__ float ex2f(float x) {
    float r; asm("ex2.approx.f32 %0, %1;" : "=f"(r) : "f"(x)); return r;
}
__device__ __forceinline__ float sinaf(float x) {
    float r; asm("sin.approx.f32 %0, %1;" : "=f"(r) : "f"(x)); return r;
}
__device__ __forceinline__ float cosaf(float x) {
    float r; asm("cos.approx.f32 %0, %1;" : "=f"(r) : "f"(x)); return r;
}

// ---- device-global scratch ---------------------------------------------------
// 7 float4 (= 7 ulonglong2) per compacted gabor, every value DUPLICATED (x,x):
//   [7n+0]=(uc,uc,vc,vc)  [7n+1]=(cr,cr,sr,sr)    [7n+2]=(i2s,i2s,i2g,i2g)
//   [7n+3]=(fr,fr,A0,A0)  [7n+4]=(A1,A1,A2,A2)    [7n+5]=(nB0,nB0,nB1,nB1)
//   [7n+6]=(nB2,nB2,0,0)
// Read via __ldg broadcasts — L1-resident, shared SM-wide (no per-block smem copy).
__device__ float4 g_k[NG * 7];
__device__ int    g_cnt;

__device__ __forceinline__ float clampf(float x, float lo, float hi) {
    return fminf(fmaxf(x, lo), hi);
}

// ---- prep kernel: clamp params, build coefficients, compact dead gabors -----
__global__ void prep_kernel(const float* __restrict__ u,
                            const float* __restrict__ v,
                            const float* __restrict__ theta,
                            const float* __restrict__ rsig,
                            const float* __restrict__ rfreq,
                            const float* __restrict__ gam,
                            const float* __restrict__ psi,
                            const float* __restrict__ amp) {
    int n = threadIdx.x;   // 256 threads, 1 block

    float uc = clampf(u[n], -1.f, 1.f);
    float vc = clampf(v[n], -1.f, 1.f);
    float th = clampf(theta[n], -2.f, 2.f) * TWOPI_F;
    float sr, cr;
    sincosf(th, &sr, &cr);

    float sg  = clampf(rsig[n], 1e-5f, 5.f);
    float gm  = clampf(gam[n],  1e-5f, 5.f);
    float i2s = -1.f / (2.f * sg * sg);
    float i2g = -1.f / (2.f * gm * gm);
    float fr  = TWOPI_F / expf(rfreq[n]);

    float A[3], nB[3];
    bool keep = false;
    #pragma unroll
    for (int c = 0; c < 3; ++c) {
        float a  = clampf(amp[3 * n + c], 0.f, 1.f);
        float ph = clampf(psi[3 * n + c], -1.f, 1.f) * TWOPI_F;
        float sp, cp;
        sincosf(ph, &sp, &cp);
        A[c]  =  a * cp;
        nB[c] = -a * sp;
        keep  = keep || (a > 0.f);
    }

    unsigned m = __ballot_sync(0xffffffffu, keep);
    __shared__ int wcnt[8];
    int wid = n >> 5, lid = n & 31;
    if (lid == 0) wcnt[wid] = __popc(m);
    __syncthreads();
    int basew = 0;
    for (int w = 0; w < wid; ++w) basew += wcnt[w];
    if (keep) {
        int p = basew + __popc(m & ((1u << lid) - 1u));
        g_k[7 * p + 0] = make_float4(uc,  uc,  vc,  vc);
        g_k[7 * p + 1] = make_float4(cr,  cr,  sr,  sr);
        g_k[7 * p + 2] = make_float4(i2s, i2s, i2g, i2g);
        g_k[7 * p + 3] = make_float4(fr,  fr,  A[0], A[0]);
        g_k[7 * p + 4] = make_float4(A[1], A[1], A[2], A[2]);
        g_k[7 * p + 5] = make_float4(nB[0], nB[0], nB[1], nB[1]);
        g_k[7 * p + 6] = make_float4(nB[2], nB[2], 0.f, 0.f);
    }
    __syncthreads();
    if (n == 0) {
        int tot = 0;
        #pragma unroll
        for (int w = 0; w < 8; ++w) tot += wcnt[w];
        g_cnt = tot;
    }
}

// ---- main kernel: params via L1 (__ldg), split gabor loop, smem reduction ------
__global__ void __launch_bounds__(TB)
gabor_kernel(const float* __restrict__ gx,
             const float* __restrict__ gy,
             float* __restrict__ out) {
    __shared__ F2 s_part[GTH * 3];         // 1.5 KB high-half partials

    const int cnt  = g_cnt;
    const int half = threadIdx.x >> 6;       // 0: warps 0-1, 1: warps 2-3
    const int pt   = threadIdx.x & (GTH - 1);
    const int base = blockIdx.x * PPB;
    const int idx0 = base + pt;
    const int idx1 = base + GTH + pt;

    const F2 pxP = f2pack(gx[idx0], gx[idx1]);
    const F2 pyP = f2pack(gy[idx0], gy[idx1]);

    const F2 ZERO   = 0ULL;
    const F2 L2EP   = f2pack(L2E_F, L2E_F);
    const F2 I2PIP  = f2pack(INV2PI_F, INV2PI_F);
    const F2 RC1NP  = f2pack(-RC1, -RC1);
    const F2 RC2NP  = f2pack(-RC2, -RC2);
    const F2 MAGICP = f2pack(MAGIC_F, MAGIC_F);

    F2 acc0 = 0ULL, acc1 = 0ULL, acc2 = 0ULL;

    const int cnt2 = (cnt + 1) >> 1;
    const int n0 = half ? cnt2 : 0;
    const int n1 = half ? cnt  : cnt2;

    const ulonglong2* __restrict__ kb =
        reinterpret_cast<const ulonglong2*>(g_k);

    for (int n = n0; n < n1; ++n) {
        const ulonglong2* kn = kb + 7 * n;
        ulonglong2 q0 = __ldg(kn + 0);   // (ucP, vcP)
        ulonglong2 q1 = __ldg(kn + 1);   // (crP, srP)
        ulonglong2 q2 = __ldg(kn + 2);   // (i2sP, i2gP)

        // bitwise-per-half identical to the scalar reference path
        F2 dx = f2sub(pxP, q0.x);
        F2 dy = f2sub(pyP, q0.y);
        F2 xr = f2fma(dx, q1.x, f2mul(dy, q1.y));
        F2 yr = f2fma(dy, q1.x, f2sub(ZERO, f2mul(dx, q1.y)));
        F2 arg = f2fma(f2mul(yr, yr), q2.y, f2mul(f2mul(xr, xr), q2.x));

        float a0, a1;
        f2unpack(arg, a0, a1);
        // warp-level skip: dropped contributions < e^-17 each, total < ~1e-5
        if (!__any_sync(0xffffffffu, fmaxf(a0, a1) > -17.0f)) continue;

        ulonglong2 q3 = __ldg(kn + 3);   // (frP, A0P)
        ulonglong2 q4 = __ldg(kn + 4);   // (A1P, A2P)
        ulonglong2 q5 = __ldg(kn + 5);   // (nB0P, nB1P)
        ulonglong2 q6 = __ldg(kn + 6);   // (nB2P, --)

        // gaussian: exactly __expf(arg) per half
        float e0, e1;
        f2unpack(f2mul(arg, L2EP), e0, e1);
        float g0 = ex2f(e0), g1 = ex2f(e1);

        // carrier phase: fx = freq*xr (frozen expression tree)
        F2 fxP = f2mul(q3.x, xr);
        float fx0, fx1;
        f2unpack(fxP, fx0, fx1);

        // round-to-nearest k via magic-number add/sub (|fx*inv2pi| < 2^22 here);
        // tie-edge k±1 only shifts r by 2pi (same sin/cos). Then 2-term Cody-Waite.
        F2 kP = f2sub(f2fma(fxP, I2PIP, MAGICP), MAGICP);
        F2 rP = f2fma(kP, RC1NP, fxP);
        rP = f2fma(kP, RC2NP, rP);
        float r0, r1;
        f2unpack(rP, r0, r1);

        // rare extreme-frequency gabor: fp64 reduction per half
        if (fabsf(fx0) >= 1.0e7f) {
            double xd = (double)fx0, q = rint(xd * INV2PI_D);
            r0 = (float)fma(q, -TWOPI_D, xd);
        }
        if (fabsf(fx1) >= 1.0e7f) {
            double xd = (double)fx1, q = rint(xd * INV2PI_D);
            r1 = (float)fma(q, -TWOPI_D, xd);
        }

        float s0 = sinaf(r0), c0 = cosaf(r0);
        float s1 = sinaf(r1), c1 = cosaf(r1);

        F2 gcP = f2pack(g0 * c0, g1 * c1);
        F2 gsP = f2pack(g0 * s0, g1 * s1);

        acc0 = f2fma(gcP, q3.y, f2fma(gsP, q5.x, acc0));
        acc1 = f2fma(gcP, q4.x, f2fma(gsP, q5.y, acc1));
        acc2 = f2fma(gcP, q4.y, f2fma(gsP, q6.x, acc2));
    }

    // combine halves: high half publishes, low half reduces + stores
    if (half) {
        s_part[pt]           = acc0;
        s_part[pt + GTH]     = acc1;
        s_part[pt + 2 * GTH] = acc2;
    }
    __syncthreads();
    if (!half) {
        acc0 = f2add(acc0, s_part[pt]);
        acc1 = f2add(acc1, s_part[pt + GTH]);
        acc2 = f2add(acc2, s_part[pt + 2 * GTH]);

        float v0, v1;
        f2unpack(acc0, v0, v1);
        out[idx0] = clampf(v0, -1.f, 1.f);
        out[idx1] = clampf(v1, -1.f, 1.f);
        f2unpack(acc1, v0, v1);
        out[HW + idx0] = clampf(v0, -1.f, 1.f);
        out[HW + idx1] = clampf(v1, -1.f, 1.f);
        f2unpack(acc2, v0, v1);
        out[2 * HW + idx0] = clampf(v0, -1.f, 1.f);
        out[2 * HW + idx1] = clampf(v1, -1.f, 1.f);
    }
}

// ---- launch ----------------------------------------------------------------------
extern "C" void kernel_launch(void* const* d_in, const int* in_sizes, int n_in,
                              void* d_out, int out_size) {
    const float* gx    = (const float*)d_in[0];
    const float* gy    = (const float*)d_in[1];
    const float* u     = (const float*)d_in[2];
    const float* v     = (const float*)d_in[3];
    const float* theta = (const float*)d_in[4];
    const float* rfreq = (const float*)d_in[6];
    const float* rsig  = (const float*)d_in[5];
    const float* gam   = (const float*)d_in[7];
    const float* psi   = (const float*)d_in[8];
    const float* amp   = (const float*)d_in[9];
    float* out = (float*)d_out;

    prep_kernel<<<1, NG>>>(u, v, theta, rsig, rfreq, gam, psi, amp);
    gabor_kernel<<<NBLK, TB>>>(gx, gy, out);
}

// round 8
// speedup vs baseline: 1.5417x; 1.5417x over previous
#include <cuda_runtime.h>
#include <math.h>

#define NG   256
#define HGT  512
#define WID  512
#define HW   (HGT * WID)
#define TB   256
#define QTH  64                // threads per gabor-quarter
#define PPB  128               // pixels per block (2 per pixel-thread)
#define NBLK (HW / PPB)        // 2048

// ---- constants -------------------------------------------------------------
constexpr double TWOPI_D  = 6.283185307179586476925286766559;
constexpr float  TWOPI_F  = (float)TWOPI_D;
constexpr float  RC1      = (float)TWOPI_D;
constexpr float  RC2      = (float)(TWOPI_D - (double)RC1);
constexpr float  INV2PI_F = (float)(1.0 / TWOPI_D);
constexpr double INV2PI_D = 1.0 / TWOPI_D;
constexpr float  L2E_F    = 1.4426950408889634f;   // == __expf's log2(e)
constexpr float  MAGIC_F  = 12582912.0f;           // 2^23 + 2^22: rne rounder

// ---- packed f32x2 helpers (each half bitwise identical to scalar op) --------
typedef unsigned long long F2;

__device__ __forceinline__ F2 f2pack(float lo, float hi) {
    F2 r; asm("mov.b64 %0, {%1, %2};" : "=l"(r) : "f"(lo), "f"(hi)); return r;
}
__device__ __forceinline__ void f2unpack(F2 v, float& lo, float& hi) {
    asm("mov.b64 {%0, %1}, %2;" : "=f"(lo), "=f"(hi) : "l"(v));
}
__device__ __forceinline__ F2 f2add(F2 a, F2 b) {
    F2 r; asm("add.rn.f32x2 %0, %1, %2;" : "=l"(r) : "l"(a), "l"(b)); return r;
}
__device__ __forceinline__ F2 f2sub(F2 a, F2 b) {
    F2 r; asm("sub.rn.f32x2 %0, %1, %2;" : "=l"(r) : "l"(a), "l"(b)); return r;
}
__device__ __forceinline__ F2 f2mul(F2 a, F2 b) {
    F2 r; asm("mul.rn.f32x2 %0, %1, %2;" : "=l"(r) : "l"(a), "l"(b)); return r;
}
__device__ __forceinline__ F2 f2fma(F2 a, F2 b, F2 c) {
    F2 r; asm("fma.rn.f32x2 %0, %1, %2, %3;" : "=l"(r) : "l"(a), "l"(b), "l"(c)); return r;
}
__device__ __forceinline__ float ex2f(float x) {
    float r; asm("ex2.approx.f32 %0, %1;" : "=f"(r) : "f"(x)); return r;
}
__device__ __forceinline__ float sinaf(float x) {
    float r; asm("sin.approx.f32 %0, %1;" : "=f"(r) : "f"(x)); return r;
}
__device__ __forceinline__ float cosaf(float x) {
    float r; asm("cos.approx.f32 %0, %1;" : "=f"(r) : "f"(x)); return r;
}

// ---- device-global scratch ---------------------------------------------------
// 7 float4 per compacted gabor, every value DUPLICATED into an (x,x) pair:
//   [7n+0]=(uc,uc,vc,vc)  [7n+1]=(cr,cr,sr,sr)    [7n+2]=(i2s,i2s,i2g,i2g)
//   [7n+3]=(fr,fr,A0,A0)  [7n+4]=(A1,A1,A2,A2)    [7n+5]=(nB0,nB0,nB1,nB1)
//   [7n+6]=(nB2,nB2,0,0)
__device__ float4 g_k[NG * 7];
__device__ int    g_cnt;

__device__ __forceinline__ float clampf(float x, float lo, float hi) {
    return fminf(fmaxf(x, lo), hi);
}

// ---- prep kernel: clamp params, build coefficients, compact dead gabors -----
__global__ void prep_kernel(const float* __restrict__ u,
                            const float* __restrict__ v,
                            const float* __restrict__ theta,
                            const float* __restrict__ rsig,
                            const float* __restrict__ rfreq,
                            const float* __restrict__ gam,
                            const float* __restrict__ psi,
                            const float* __restrict__ amp) {
    int n = threadIdx.x;   // 256 threads, 1 block

    float uc = clampf(u[n], -1.f, 1.f);
    float vc = clampf(v[n], -1.f, 1.f);
    float th = clampf(theta[n], -2.f, 2.f) * TWOPI_F;
    float sr, cr;
    sincosf(th, &sr, &cr);

    float sg  = clampf(rsig[n], 1e-5f, 5.f);
    float gm  = clampf(gam[n],  1e-5f, 5.f);
    float i2s = -1.f / (2.f * sg * sg);
    float i2g = -1.f / (2.f * gm * gm);
    float fr  = TWOPI_F / expf(rfreq[n]);

    float A[3], nB[3];
    bool keep = false;
    #pragma unroll
    for (int c = 0; c < 3; ++c) {
        float a  = clampf(amp[3 * n + c], 0.f, 1.f);
        float ph = clampf(psi[3 * n + c], -1.f, 1.f) * TWOPI_F;
        float sp, cp;
        sincosf(ph, &sp, &cp);
        A[c]  =  a * cp;
        nB[c] = -a * sp;
        keep  = keep || (a > 0.f);
    }

    unsigned m = __ballot_sync(0xffffffffu, keep);
    __shared__ int wcnt[8];
    int wid = n >> 5, lid = n & 31;
    if (lid == 0) wcnt[wid] = __popc(m);
    __syncthreads();
    int basew = 0;
    for (int w = 0; w < wid; ++w) basew += wcnt[w];
    if (keep) {
        int p = basew + __popc(m & ((1u << lid) - 1u));
        g_k[7 * p + 0] = make_float4(uc,  uc,  vc,  vc);
        g_k[7 * p + 1] = make_float4(cr,  cr,  sr,  sr);
        g_k[7 * p + 2] = make_float4(i2s, i2s, i2g, i2g);
        g_k[7 * p + 3] = make_float4(fr,  fr,  A[0], A[0]);
        g_k[7 * p + 4] = make_float4(A[1], A[1], A[2], A[2]);
        g_k[7 * p + 5] = make_float4(nB[0], nB[0], nB[1], nB[1]);
        g_k[7 * p + 6] = make_float4(nB[2], nB[2], 0.f, 0.f);
    }
    __syncthreads();
    if (n == 0) {
        int tot = 0;
        #pragma unroll
        for (int w = 0; w < 8; ++w) tot += wcnt[w];
        g_cnt = tot;
    }
}

// ---- main kernel: 4-way gabor split, params in smem, partials alias params ----
__global__ void __launch_bounds__(TB, 8)
gabor_kernel(const float* __restrict__ gx,
             const float* __restrict__ gy,
             float* __restrict__ out) {
    // 28 KB param table; re-used as reduction scratch after the loop
    __shared__ ulonglong2 s_k[NG * 7];

    const int cnt = g_cnt;
    {
        const ulonglong2* gk = reinterpret_cast<const ulonglong2*>(g_k);
        for (int i = threadIdx.x; i < 7 * cnt; i += TB) s_k[i] = gk[i];
    }
    __syncthreads();

    const int quarter = threadIdx.x >> 6;     // 0..3 (gabor range quarter)
    const int pt      = threadIdx.x & (QTH - 1);
    const int base    = blockIdx.x * PPB;
    const int idx0    = base + pt;
    const int idx1    = base + QTH + pt;

    const F2 pxP = f2pack(gx[idx0], gx[idx1]);
    const F2 pyP = f2pack(gy[idx0], gy[idx1]);

    const F2 ZERO   = 0ULL;
    const F2 L2EP   = f2pack(L2E_F, L2E_F);
    const F2 I2PIP  = f2pack(INV2PI_F, INV2PI_F);
    const F2 RC1NP  = f2pack(-RC1, -RC1);
    const F2 RC2NP  = f2pack(-RC2, -RC2);
    const F2 MAGICP = f2pack(MAGIC_F, MAGIC_F);

    F2 acc0 = 0ULL, acc1 = 0ULL, acc2 = 0ULL;

    const int n0 = (cnt * quarter) >> 2;
    const int n1 = (cnt * (quarter + 1)) >> 2;

    for (int n = n0; n < n1; ++n) {
        const ulonglong2* kn = &s_k[7 * n];
        ulonglong2 q0 = kn[0];   // (ucP, vcP)
        ulonglong2 q1 = kn[1];   // (crP, srP)
        ulonglong2 q2 = kn[2];   // (i2sP, i2gP)

        // bitwise-per-half identical to the scalar reference path
        F2 dx = f2sub(pxP, q0.x);
        F2 dy = f2sub(pyP, q0.y);
        F2 xr = f2fma(dx, q1.x, f2mul(dy, q1.y));
        F2 yr = f2fma(dy, q1.x, f2sub(ZERO, f2mul(dx, q1.y)));
        F2 arg = f2fma(f2mul(yr, yr), q2.y, f2mul(f2mul(xr, xr), q2.x));

        float a0, a1;
        f2unpack(arg, a0, a1);
        // warp-level skip: dropped contributions < e^-17 each, total < ~1e-5
        if (!__any_sync(0xffffffffu, fmaxf(a0, a1) > -17.0f)) continue;

        ulonglong2 q3 = kn[3];   // (frP, A0P)
        ulonglong2 q4 = kn[4];   // (A1P, A2P)
        ulonglong2 q5 = kn[5];   // (nB0P, nB1P)
        ulonglong2 q6 = kn[6];   // (nB2P, --)

        // gaussian: exactly __expf(arg) per half
        float e0, e1;
        f2unpack(f2mul(arg, L2EP), e0, e1);
        float g0 = ex2f(e0), g1 = ex2f(e1);

        // carrier phase: fx = freq*xr (frozen expression tree)
        F2 fxP = f2mul(q3.x, xr);
        float fx0, fx1;
        f2unpack(fxP, fx0, fx1);

        // round-to-nearest k via magic add/sub, then 2-term Cody-Waite to [-pi,pi]
        F2 kP = f2sub(f2fma(fxP, I2PIP, MAGICP), MAGICP);
        F2 rP = f2fma(kP, RC1NP, fxP);
        rP = f2fma(kP, RC2NP, rP);
        float r0, r1;
        f2unpack(rP, r0, r1);

        // rare extreme-frequency gabor: fp64 reduction per half
        if (fabsf(fx0) >= 1.0e7f) {
            double xd = (double)fx0, q = rint(xd * INV2PI_D);
            r0 = (float)fma(q, -TWOPI_D, xd);
        }
        if (fabsf(fx1) >= 1.0e7f) {
            double xd = (double)fx1, q = rint(xd * INV2PI_D);
            r1 = (float)fma(q, -TWOPI_D, xd);
        }

        float s0 = sinaf(r0), c0 = cosaf(r0);
        float s1 = sinaf(r1), c1 = cosaf(r1);

        F2 gcP = f2pack(g0 * c0, g1 * c1);
        F2 gsP = f2pack(g0 * s0, g1 * s1);

        acc0 = f2fma(gcP, q3.y, f2fma(gsP, q5.x, acc0));
        acc1 = f2fma(gcP, q4.x, f2fma(gsP, q5.y, acc1));
        acc2 = f2fma(gcP, q4.y, f2fma(gsP, q6.x, acc2));
    }

    // reduction: quarters 1-3 publish partials into the (now dead) param smem
    __syncthreads();                       // all quarters done reading params
    F2* s_part = reinterpret_cast<F2*>(s_k);   // 3*3*QTH F2 = 4.5 KB < 28 KB
    if (quarter) {
        const int b = (quarter - 1) * 3 * QTH;
        s_part[b + pt]           = acc0;
        s_part[b + QTH + pt]     = acc1;
        s_part[b + 2 * QTH + pt] = acc2;
    }
    __syncthreads();
    if (quarter == 0) {
        #pragma unroll
        for (int qq = 0; qq < 3; ++qq) {
            const int b = qq * 3 * QTH;
            acc0 = f2add(acc0, s_part[b + pt]);
            acc1 = f2add(acc1, s_part[b + QTH + pt]);
            acc2 = f2add(acc2, s_part[b + 2 * QTH + pt]);
        }
        float v0, v1;
        f2unpack(acc0, v0, v1);
        out[idx0] = clampf(v0, -1.f, 1.f);
        out[idx1] = clampf(v1, -1.f, 1.f);
        f2unpack(acc1, v0, v1);
        out[HW + idx0] = clampf(v0, -1.f, 1.f);
        out[HW + idx1] = clampf(v1, -1.f, 1.f);
        f2unpack(acc2, v0, v1);
        out[2 * HW + idx0] = clampf(v0, -1.f, 1.f);
        out[2 * HW + idx1] = clampf(v1, -1.f, 1.f);
    }
}

// ---- launch ----------------------------------------------------------------------
extern "C" void kernel_launch(void* const* d_in, const int* in_sizes, int n_in,
                              void* d_out, int out_size) {
    const float* gx    = (const float*)d_in[0];
    const float* gy    = (const float*)d_in[1];
    const float* u     = (const float*)d_in[2];
    const float* v     = (const float*)d_in[3];
    const float* theta = (const float*)d_in[4];
    const float* rsig  = (const float*)d_in[5];
    const float* rfreq = (const float*)d_in[6];
    const float* gam   = (const float*)d_in[7];
    const float* psi   = (const float*)d_in[8];
    const float* amp   = (const float*)d_in[9];
    float* out = (float*)d_out;

    prep_kernel<<<1, NG>>>(u, v, theta, rsig, rfreq, gam, psi, amp);
    gabor_kernel<<<NBLK, TB>>>(gx, gy, out);
}

// round 9
// speedup vs baseline: 1.9081x; 1.2377x over previous
#include <cuda_runtime.h>
#include <math.h>

#define NG   256
#define HGT  512
#define WID  512
#define HW   (HGT * WID)
#define TB   256
#define QTH  64                // threads per gabor-quarter
#define PPB  128               // pixels per block (2 per pixel-thread)
#define NBLK (HW / PPB)        // 2048

// ---- constants -------------------------------------------------------------
constexpr double TWOPI_D  = 6.283185307179586476925286766559;
constexpr float  TWOPI_F  = (float)TWOPI_D;
constexpr float  RC1      = (float)TWOPI_D;
constexpr float  RC2      = (float)(TWOPI_D - (double)RC1);
constexpr float  INV2PI_F = (float)(1.0 / TWOPI_D);
constexpr double INV2PI_D = 1.0 / TWOPI_D;
constexpr float  L2E_F    = 1.4426950408889634f;   // == __expf's log2(e)
constexpr float  MAGIC_F  = 12582912.0f;           // 2^23 + 2^22: rne rounder
constexpr float  BTH      = 5.830951894845301f;    // sqrt(34): |axis|/width bound
constexpr float  FR_FAST  = 3.0e6f;  // freq*|xr|max(2.83) < 1e7 -> no fp64 path

// ---- packed f32x2 helpers (each half bitwise identical to scalar op) --------
typedef unsigned long long F2;

__device__ __forceinline__ F2 f2pack(float lo, float hi) {
    F2 r; asm("mov.b64 %0, {%1, %2};" : "=l"(r) : "f"(lo), "f"(hi)); return r;
}
__device__ __forceinline__ void f2unpack(F2 v, float& lo, float& hi) {
    asm("mov.b64 {%0, %1}, %2;" : "=f"(lo), "=f"(hi) : "l"(v));
}
__device__ __forceinline__ F2 f2add(F2 a, F2 b) {
    F2 r; asm("add.rn.f32x2 %0, %1, %2;" : "=l"(r) : "l"(a), "l"(b)); return r;
}
__device__ __forceinline__ F2 f2sub(F2 a, F2 b) {
    F2 r; asm("sub.rn.f32x2 %0, %1, %2;" : "=l"(r) : "l"(a), "l"(b)); return r;
}
__device__ __forceinline__ F2 f2mul(F2 a, F2 b) {
    F2 r; asm("mul.rn.f32x2 %0, %1, %2;" : "=l"(r) : "l"(a), "l"(b)); return r;
}
__device__ __forceinline__ F2 f2fma(F2 a, F2 b, F2 c) {
    F2 r; asm("fma.rn.f32x2 %0, %1, %2, %3;" : "=l"(r) : "l"(a), "l"(b), "l"(c)); return r;
}
__device__ __forceinline__ float ex2f(float x) {
    float r; asm("ex2.approx.f32 %0, %1;" : "=f"(r) : "f"(x)); return r;
}
__device__ __forceinline__ float sinaf(float x) {
    float r; asm("sin.approx.f32 %0, %1;" : "=f"(r) : "f"(x)); return r;
}
__device__ __forceinline__ float cosaf(float x) {
    float r; asm("cos.approx.f32 %0, %1;" : "=f"(r) : "f"(x)); return r;
}

// ---- device-global scratch ---------------------------------------------------
// 7 float4 per compacted gabor, every value DUPLICATED into an (x,x) pair:
//   [7n+0]=(uc,uc,vc,vc)  [7n+1]=(cr,cr,sr,sr)    [7n+2]=(i2s,i2s,i2g,i2g)
//   [7n+3]=(fr,fr,A0,A0)  [7n+4]=(A1,A1,A2,A2)    [7n+5]=(nB0,nB0,nB1,nB1)
//   [7n+6]=(nB2,nB2,0,0)
// Plus per-gabor stage-1 gate line: g_t[n]=(t0,t1,t2,0); w=px*t0+py*t1+t2 is the
// thinnest-axis coordinate scaled by 1/width; |w|>sqrt(34) == that axis alone
// already drives the gaussian below e^-17.
// Order: "fast" gabors (freq < 3e6 -> never need fp64 reduction) first,
// then slow ones; split at g_nfast.
__device__ float4 g_k[NG * 7];
__device__ float4 g_t[NG];
__device__ int    g_cnt;
__device__ int    g_nfast;

__device__ __forceinline__ float clampf(float x, float lo, float hi) {
    return fminf(fmaxf(x, lo), hi);
}

// ---- prep kernel: clamp, build coefficients, classify, compact ---------------
__global__ void prep_kernel(const float* __restrict__ u,
                            const float* __restrict__ v,
                            const float* __restrict__ theta,
                            const float* __restrict__ rsig,
                            const float* __restrict__ rfreq,
                            const float* __restrict__ gam,
                            const float* __restrict__ psi,
                            const float* __restrict__ amp) {
    int n = threadIdx.x;   // 256 threads, 1 block

    float uc = clampf(u[n], -1.f, 1.f);
    float vc = clampf(v[n], -1.f, 1.f);
    float th = clampf(theta[n], -2.f, 2.f) * TWOPI_F;
    float sr, cr;
    sincosf(th, &sr, &cr);

    float sg  = clampf(rsig[n], 1e-5f, 5.f);
    float gm  = clampf(gam[n],  1e-5f, 5.f);
    float i2s = -1.f / (2.f * sg * sg);
    float i2g = -1.f / (2.f * gm * gm);
    float fr  = TWOPI_F / expf(rfreq[n]);

    // stage-1 gate: thinnest axis, coords scaled by 1/width
    float t0, t1, t2;
    if (sg <= gm) {
        t0 = cr / sg;  t1 = sr / sg;  t2 = -(uc * cr + vc * sr) / sg;
    } else {
        t0 = -sr / gm; t1 = cr / gm;  t2 =  (uc * sr - vc * cr) / gm;
    }

    float A[3], nB[3];
    bool keep = false;
    #pragma unroll
    for (int c = 0; c < 3; ++c) {
        float a  = clampf(amp[3 * n + c], 0.f, 1.f);
        float ph = clampf(psi[3 * n + c], -1.f, 1.f) * TWOPI_F;
        float sp, cp;
        sincosf(ph, &sp, &cp);
        A[c]  =  a * cp;
        nB[c] = -a * sp;
        keep  = keep || (a > 0.f);
    }

    bool fast = fr < FR_FAST;  // |fx| <= fr*2.83 < 1e7: fp64 path unreachable

    // deterministic dual compaction: fast-kept first, slow-kept after
    unsigned mF = __ballot_sync(0xffffffffu, keep && fast);
    unsigned mS = __ballot_sync(0xffffffffu, keep && !fast);
    __shared__ int wf[8], ws[8];
    int wid = n >> 5, lid = n & 31;
    if (lid == 0) { wf[wid] = __popc(mF); ws[wid] = __popc(mS); }
    __syncthreads();
    int totF = 0, totS = 0, baseF = 0, baseS = 0;
    #pragma unroll
    for (int w = 0; w < 8; ++w) {
        if (w < wid) { baseF += wf[w]; baseS += ws[w]; }
        totF += wf[w]; totS += ws[w];
    }
    if (keep) {
        unsigned lane = (1u << lid) - 1u;
        int p = fast ? (baseF + __popc(mF & lane))
                     : (totF + baseS + __popc(mS & lane));
        g_k[7 * p + 0] = make_float4(uc,  uc,  vc,  vc);
        g_k[7 * p + 1] = make_float4(cr,  cr,  sr,  sr);
        g_k[7 * p + 2] = make_float4(i2s, i2s, i2g, i2g);
        g_k[7 * p + 3] = make_float4(fr,  fr,  A[0], A[0]);
        g_k[7 * p + 4] = make_float4(A[1], A[1], A[2], A[2]);
        g_k[7 * p + 5] = make_float4(nB[0], nB[0], nB[1], nB[1]);
        g_k[7 * p + 6] = make_float4(nB[2], nB[2], 0.f, 0.f);
        g_t[p] = make_float4(t0, t1, t2, 0.f);
    }
    if (n == 0) { g_cnt = totF + totS; g_nfast = totF; }
}

// ---- core loop over a gabor range; FP64 = include extreme-freq fallback -------
template<bool FP64>
__device__ __forceinline__ void gabor_range(
    int n0, int n1,
    const float4* __restrict__ s_t, const ulonglong2* __restrict__ s_k,
    float px0, float py0, float px1, float py1,
    F2 pxP, F2 pyP, F2& acc0, F2& acc1, F2& acc2)
{
    const F2 ZERO   = 0ULL;
    const F2 L2EP   = f2pack(L2E_F, L2E_F);
    const F2 I2PIP  = f2pack(INV2PI_F, INV2PI_F);
    const F2 RC1NP  = f2pack(-RC1, -RC1);
    const F2 RC2NP  = f2pack(-RC2, -RC2);
    const F2 MAGICP = f2pack(MAGIC_F, MAGIC_F);

    for (int n = n0; n < n1; ++n) {
        // stage-1 gate: thinnest-axis line test (skip-only; not used numerically)
        float4 t = s_t[n];
        float w0 = fmaf(px0, t.x, fmaf(py0, t.y, t.z));
        float w1 = fmaf(px1, t.x, fmaf(py1, t.y, t.z));
        if (!__any_sync(0xffffffffu, fminf(fabsf(w0), fabsf(w1)) < BTH)) continue;

        const ulonglong2* kn = &s_k[7 * n];
        ulonglong2 q0 = kn[0];   // (ucP, vcP)
        ulonglong2 q1 = kn[1];   // (crP, srP)
        ulonglong2 q2 = kn[2];   // (i2sP, i2gP)

        // frozen expression tree — bitwise-per-half identical to the reference
        F2 dx = f2sub(pxP, q0.x);
        F2 dy = f2sub(pyP, q0.y);
        F2 xr = f2fma(dx, q1.x, f2mul(dy, q1.y));
        F2 yr = f2fma(dy, q1.x, f2sub(ZERO, f2mul(dx, q1.y)));
        F2 arg = f2fma(f2mul(yr, yr), q2.y, f2mul(f2mul(xr, xr), q2.x));

        float a0, a1;
        f2unpack(arg, a0, a1);
        // stage-2 exact gate: dropped contributions < e^-17 each, total < ~1e-5
        if (!__any_sync(0xffffffffu, fmaxf(a0, a1) > -17.0f)) continue;

        ulonglong2 q3 = kn[3];   // (frP, A0P)
        ulonglong2 q4 = kn[4];   // (A1P, A2P)
        ulonglong2 q5 = kn[5];   // (nB0P, nB1P)
        ulonglong2 q6 = kn[6];   // (nB2P, --)

        // gaussian: exactly __expf(arg) per half
        float e0, e1;
        f2unpack(f2mul(arg, L2EP), e0, e1);
        float g0 = ex2f(e0), g1 = ex2f(e1);

        // carrier phase: fx = freq*xr (frozen)
        F2 fxP = f2mul(q3.x, xr);

        // round-to-nearest k via magic add/sub, then 2-term Cody-Waite to [-pi,pi]
        F2 kP = f2sub(f2fma(fxP, I2PIP, MAGICP), MAGICP);
        F2 rP = f2fma(kP, RC1NP, fxP);
        rP = f2fma(kP, RC2NP, rP);
        float r0, r1;
        f2unpack(rP, r0, r1);

        if (FP64) {
            // extreme-frequency gabors only (freq >= 3e6): fp64 reduction
            float fx0, fx1;
            f2unpack(fxP, fx0, fx1);
            if (fabsf(fx0) >= 1.0e7f) {
                double xd = (double)fx0, q = rint(xd * INV2PI_D);
                r0 = (float)fma(q, -TWOPI_D, xd);
            }
            if (fabsf(fx1) >= 1.0e7f) {
                double xd = (double)fx1, q = rint(xd * INV2PI_D);
                r1 = (float)fma(q, -TWOPI_D, xd);
            }
        }

        float s0 = sinaf(r0), c0 = cosaf(r0);
        float s1 = sinaf(r1), c1 = cosaf(r1);

        F2 gcP = f2pack(g0 * c0, g1 * c1);
        F2 gsP = f2pack(g0 * s0, g1 * s1);

        acc0 = f2fma(gcP, q3.y, f2fma(gsP, q5.x, acc0));
        acc1 = f2fma(gcP, q4.x, f2fma(gsP, q5.y, acc1));
        acc2 = f2fma(gcP, q4.y, f2fma(gsP, q6.x, acc2));
    }
}

// ---- main kernel: 4-way gabor split, staged gating, partials alias params -----
__global__ void __launch_bounds__(TB, 7)
gabor_kernel(const float* __restrict__ gx,
             const float* __restrict__ gy,
             float* __restrict__ out) {
    __shared__ ulonglong2 s_k[NG * 7];   // 28 KB params; reused for partials
    __shared__ float4     s_t[NG];       // 4 KB stage-1 gate lines

    const int cnt   = g_cnt;
    const int nfast = g_nfast;
    {
        const ulonglong2* gk = reinterpret_cast<const ulonglong2*>(g_k);
        for (int i = threadIdx.x; i < 7 * cnt; i += TB) s_k[i] = gk[i];
        for (int i = threadIdx.x; i < cnt; i += TB) s_t[i] = g_t[i];
    }
    __syncthreads();

    const int quarter = threadIdx.x >> 6;     // 0..3 (gabor range quarter)
    const int pt      = threadIdx.x & (QTH - 1);
    const int base    = blockIdx.x * PPB;
    const int idx0    = base + pt;
    const int idx1    = base + QTH + pt;

    const float px0 = gx[idx0], px1 = gx[idx1];
    const float py0 = gy[idx0], py1 = gy[idx1];
    const F2 pxP = f2pack(px0, px1);
    const F2 pyP = f2pack(py0, py1);

    F2 acc0 = 0ULL, acc1 = 0ULL, acc2 = 0ULL;

    // fast gabors [0, nfast) — no fp64 code compiled in
    {
        const int f0 = (nfast * quarter) >> 2;
        const int f1 = (nfast * (quarter + 1)) >> 2;
        gabor_range<false>(f0, f1, s_t, s_k, px0, py0, px1, py1,
                           pxP, pyP, acc0, acc1, acc2);
    }
    // slow gabors [nfast, cnt) — with fp64 fallback (usually 0-2 gabors)
    {
        const int ns = cnt - nfast;
        const int s0 = nfast + ((ns * quarter) >> 2);
        const int s1 = nfast + ((ns * (quarter + 1)) >> 2);
        gabor_range<true>(s0, s1, s_t, s_k, px0, py0, px1, py1,
                          pxP, pyP, acc0, acc1, acc2);
    }

    // reduction: quarters 1-3 publish partials into the (now dead) param smem
    __syncthreads();
    F2* s_part = reinterpret_cast<F2*>(s_k);
    if (quarter) {
        const int b = (quarter - 1) * 3 * QTH;
        s_part[b + pt]           = acc0;
        s_part[b + QTH + pt]     = acc1;
        s_part[b + 2 * QTH + pt] = acc2;
    }
    __syncthreads();
    if (quarter == 0) {
        #pragma unroll
        for (int qq = 0; qq < 3; ++qq) {
            const int b = qq * 3 * QTH;
            acc0 = f2add(acc0, s_part[b + pt]);
            acc1 = f2add(acc1, s_part[b + QTH + pt]);
            acc2 = f2add(acc2, s_part[b + 2 * QTH + pt]);
        }
        float v0, v1;
        f2unpack(acc0, v0, v1);
        out[idx0] = clampf(v0, -1.f, 1.f);
        out[idx1] = clampf(v1, -1.f, 1.f);
        f2unpack(acc1, v0, v1);
        out[HW + idx0] = clampf(v0, -1.f, 1.f);
        out[HW + idx1] = clampf(v1, -1.f, 1.f);
        f2unpack(acc2, v0, v1);
        out[2 * HW + idx0] = clampf(v0, -1.f, 1.f);
        out[2 * HW + idx1] = clampf(v1, -1.f, 1.f);
    }
}

// ---- launch ----------------------------------------------------------------------
extern "C" void kernel_launch(void* const* d_in, const int* in_sizes, int n_in,
                              void* d_out, int out_size) {
    const float* gx    = (const float*)d_in[0];
    const float* gy    = (const float*)d_in[1];
    const float* u     = (const float*)d_in[2];
    const float* v     = (const float*)d_in[3];
    const float* theta = (const float*)d_in[4];
    const float* rsig  = (const float*)d_in[5];
    const float* rfreq = (const float*)d_in[6];
    const float* gam   = (const float*)d_in[7];
    const float* psi   = (const float*)d_in[8];
    const float* amp   = (const float*)d_in[9];
    float* out = (float*)d_out;

    prep_kernel<<<1, NG>>>(u, v, theta, rsig, rfreq, gam, psi, amp);
    gabor_kernel<<<NBLK, TB>>>(gx, gy, out);
}

// round 10
// speedup vs baseline: 1.9283x; 1.0106x over previous
#include <cuda_runtime.h>
#include <math.h>

#define NG   256
#define HGT  512
#define WID  512
#define HW   (HGT * WID)
#define TB   256
#define QTH  64                // threads per gabor-quarter
#define PPB  128               // pixels per block (2 per pixel-thread)
#define NBLK (HW / PPB)        // 2048

// ---- constants -------------------------------------------------------------
constexpr double TWOPI_D  = 6.283185307179586476925286766559;
constexpr float  TWOPI_F  = (float)TWOPI_D;
constexpr float  RC1      = (float)TWOPI_D;
constexpr float  RC2      = (float)(TWOPI_D - (double)RC1);
constexpr float  INV2PI_F = (float)(1.0 / TWOPI_D);
constexpr double INV2PI_D = 1.0 / TWOPI_D;
constexpr float  L2E_F    = 1.4426950408889634f;   // == __expf's log2(e)
constexpr float  MAGIC_F  = 12582912.0f;           // 2^23 + 2^22: rne rounder
constexpr float  BTH      = 5.830951894845301f;    // sqrt(34): axis/width bound
constexpr float  NTHL     = -24.525815695112378f;  // -17 * log2(e)
constexpr float  FR_FAST  = 3.0e6f;  // freq*|xr|max(2.83) < 1e7 -> no fp64 path
constexpr float  W_WIDE   = 0.02f;   // min(sig,gam) >= this -> gate never fires

// ---- packed f32x2 helpers (each half bitwise identical to scalar op) --------
typedef unsigned long long F2;

__device__ __forceinline__ F2 f2pack(float lo, float hi) {
    F2 r; asm("mov.b64 %0, {%1, %2};" : "=l"(r) : "f"(lo), "f"(hi)); return r;
}
__device__ __forceinline__ void f2unpack(F2 v, float& lo, float& hi) {
    asm("mov.b64 {%0, %1}, %2;" : "=f"(lo), "=f"(hi) : "l"(v));
}
__device__ __forceinline__ F2 f2add(F2 a, F2 b) {
    F2 r; asm("add.rn.f32x2 %0, %1, %2;" : "=l"(r) : "l"(a), "l"(b)); return r;
}
__device__ __forceinline__ F2 f2sub(F2 a, F2 b) {
    F2 r; asm("sub.rn.f32x2 %0, %1, %2;" : "=l"(r) : "l"(a), "l"(b)); return r;
}
__device__ __forceinline__ F2 f2mul(F2 a, F2 b) {
    F2 r; asm("mul.rn.f32x2 %0, %1, %2;" : "=l"(r) : "l"(a), "l"(b)); return r;
}
__device__ __forceinline__ F2 f2fma(F2 a, F2 b, F2 c) {
    F2 r; asm("fma.rn.f32x2 %0, %1, %2, %3;" : "=l"(r) : "l"(a), "l"(b), "l"(c)); return r;
}
__device__ __forceinline__ float ex2f(float x) {
    float r; asm("ex2.approx.f32 %0, %1;" : "=f"(r) : "f"(x)); return r;
}
__device__ __forceinline__ float sinaf(float x) {
    float r; asm("sin.approx.f32 %0, %1;" : "=f"(r) : "f"(x)); return r;
}
__device__ __forceinline__ float cosaf(float x) {
    float r; asm("cos.approx.f32 %0, %1;" : "=f"(r) : "f"(x)); return r;
}

// ---- device-global scratch ---------------------------------------------------
// 7 float4 per compacted gabor, every value DUPLICATED into an (x,x) pair:
//   [7n+0]=(uc,uc,vc,vc)  [7n+1]=(cr,cr,sr,sr)    [7n+2]=(i2sL,i2sL,i2gL,i2gL)
//   [7n+3]=(fr,fr,A0,A0)  [7n+4]=(A1,A1,A2,A2)    [7n+5]=(nB0,nB0,nB1,nB1)
//   [7n+6]=(nB2,nB2,0,0)
// i2sL = -log2(e)/(2 sig^2): gaussian = ex2(yr^2*i2gL + xr^2*i2sL) (amplitude;
// ~1ulp shifts vs reference are safe — phase tree xr->fx stays frozen).
// g_t[n]=(t0,t1,t2,0): thinnest-axis gate line, |px*t0+py*t1+t2| > sqrt(34)
// == that axis alone drives the gaussian below e^-17.
// Class layout: [0,nUA)=ungated(wide&fast)  [nUA,nFast)=gated thin&fast
//               [nFast,cnt)=slow (fp64 fallback), gated.
__device__ float4 g_k[NG * 7];
__device__ float4 g_t[NG];
__device__ int    g_cnt;
__device__ int    g_nua;
__device__ int    g_nfast;

__device__ __forceinline__ float clampf(float x, float lo, float hi) {
    return fminf(fmaxf(x, lo), hi);
}

// ---- prep kernel: clamp, build coefficients, classify, triple compaction -----
__global__ void prep_kernel(const float* __restrict__ u,
                            const float* __restrict__ v,
                            const float* __restrict__ theta,
                            const float* __restrict__ rsig,
                            const float* __restrict__ rfreq,
                            const float* __restrict__ gam,
                            const float* __restrict__ psi,
                            const float* __restrict__ amp) {
    int n = threadIdx.x;   // 256 threads, 1 block

    float uc = clampf(u[n], -1.f, 1.f);
    float vc = clampf(v[n], -1.f, 1.f);
    float th = clampf(theta[n], -2.f, 2.f) * TWOPI_F;
    float sr, cr;
    sincosf(th, &sr, &cr);

    float sg  = clampf(rsig[n], 1e-5f, 5.f);
    float gm  = clampf(gam[n],  1e-5f, 5.f);
    float i2sL = (-1.f / (2.f * sg * sg)) * L2E_F;
    float i2gL = (-1.f / (2.f * gm * gm)) * L2E_F;
    float fr  = TWOPI_F / expf(rfreq[n]);

    // stage-1 gate line: thinnest axis, coords scaled by 1/width
    float t0, t1, t2;
    if (sg <= gm) {
        t0 = cr / sg;  t1 = sr / sg;  t2 = -(uc * cr + vc * sr) / sg;
    } else {
        t0 = -sr / gm; t1 = cr / gm;  t2 =  (uc * sr - vc * cr) / gm;
    }

    float A[3], nB[3];
    bool keep = false;
    #pragma unroll
    for (int c = 0; c < 3; ++c) {
        float a  = clampf(amp[3 * n + c], 0.f, 1.f);
        float ph = clampf(psi[3 * n + c], -1.f, 1.f) * TWOPI_F;
        float sp, cp;
        sincosf(ph, &sp, &cp);
        A[c]  =  a * cp;
        nB[c] = -a * sp;
        keep  = keep || (a > 0.f);
    }

    bool fast = fr < FR_FAST;                 // fp64 path unreachable
    bool wide = fminf(sg, gm) >= W_WIDE;      // gate fires w.p. < 1e-8: drop it

    bool cUA = keep && fast && wide;          // ungated
    bool cGF = keep && fast && !wide;         // gated fast
    bool cS  = keep && !fast;                 // slow (fp64)

    unsigned mA = __ballot_sync(0xffffffffu, cUA);
    unsigned mG = __ballot_sync(0xffffffffu, cGF);
    unsigned mS = __ballot_sync(0xffffffffu, cS);
    __shared__ int wa[8], wg[8], ws[8];
    int wid = n >> 5, lid = n & 31;
    if (lid == 0) { wa[wid] = __popc(mA); wg[wid] = __popc(mG); ws[wid] = __popc(mS); }
    __syncthreads();
    int totA = 0, totG = 0, totS = 0, baseA = 0, baseG = 0, baseS = 0;
    #pragma unroll
    for (int w = 0; w < 8; ++w) {
        if (w < wid) { baseA += wa[w]; baseG += wg[w]; baseS += ws[w]; }
        totA += wa[w]; totG += wg[w]; totS += ws[w];
    }
    if (keep) {
        unsigned lane = (1u << lid) - 1u;
        int p;
        if (cUA)      p = baseA + __popc(mA & lane);
        else if (cGF) p = totA + baseG + __popc(mG & lane);
        else          p = totA + totG + baseS + __popc(mS & lane);
        g_k[7 * p + 0] = make_float4(uc,  uc,  vc,  vc);
        g_k[7 * p + 1] = make_float4(cr,  cr,  sr,  sr);
        g_k[7 * p + 2] = make_float4(i2sL, i2sL, i2gL, i2gL);
        g_k[7 * p + 3] = make_float4(fr,  fr,  A[0], A[0]);
        g_k[7 * p + 4] = make_float4(A[1], A[1], A[2], A[2]);
        g_k[7 * p + 5] = make_float4(nB[0], nB[0], nB[1], nB[1]);
        g_k[7 * p + 6] = make_float4(nB[2], nB[2], 0.f, 0.f);
        g_t[p] = make_float4(t0, t1, t2, 0.f);
    }
    if (n == 0) { g_cnt = totA + totG + totS; g_nua = totA; g_nfast = totA + totG; }
}

// ---- shared active-path body (frozen numerics) --------------------------------
__device__ __forceinline__ void gabor_core(
    const ulonglong2* kn, F2 xr, F2 argL,
    F2 I2PIP, F2 RC1NP, F2 RC2NP, F2 MAGICP, bool FP64,
    F2& acc0, F2& acc1, F2& acc2)
{
    ulonglong2 q3 = kn[3];   // (frP, A0P)
    ulonglong2 q4 = kn[4];   // (A1P, A2P)
    ulonglong2 q5 = kn[5];   // (nB0P, nB1P)
    ulonglong2 q6 = kn[6];   // (nB2P, --)

    // gaussian (amplitude): ex2 of log2-domain arg
    float e0, e1;
    f2unpack(argL, e0, e1);
    float g0 = ex2f(e0), g1 = ex2f(e1);

    // carrier phase: fx = freq*xr (frozen expression tree)
    F2 fxP = f2mul(q3.x, xr);

    // round-to-nearest k via magic add/sub, then 2-term Cody-Waite to [-pi,pi]
    F2 kP = f2sub(f2fma(fxP, I2PIP, MAGICP), MAGICP);
    F2 rP = f2fma(kP, RC1NP, fxP);
    rP = f2fma(kP, RC2NP, rP);
    float r0, r1;
    f2unpack(rP, r0, r1);

    if (FP64) {
        float fx0, fx1;
        f2unpack(fxP, fx0, fx1);
        if (fabsf(fx0) >= 1.0e7f) {
            double xd = (double)fx0, q = rint(xd * INV2PI_D);
            r0 = (float)fma(q, -TWOPI_D, xd);
        }
        if (fabsf(fx1) >= 1.0e7f) {
            double xd = (double)fx1, q = rint(xd * INV2PI_D);
            r1 = (float)fma(q, -TWOPI_D, xd);
        }
    }

    float s0 = sinaf(r0), c0 = cosaf(r0);
    float s1 = sinaf(r1), c1 = cosaf(r1);

    F2 gcP = f2pack(g0 * c0, g1 * c1);
    F2 gsP = f2pack(g0 * s0, g1 * s1);

    acc0 = f2fma(gcP, q3.y, f2fma(gsP, q5.x, acc0));
    acc1 = f2fma(gcP, q4.x, f2fma(gsP, q5.y, acc1));
    acc2 = f2fma(gcP, q4.y, f2fma(gsP, q6.x, acc2));
}

// ---- main kernel ----------------------------------------------------------------
__global__ void __launch_bounds__(TB, 6)
gabor_kernel(const float* __restrict__ gx,
             const float* __restrict__ gy,
             float* __restrict__ out) {
    __shared__ ulonglong2 s_k[NG * 7];   // 28 KB params; reused for partials
    __shared__ float4     s_t[NG];       // 4 KB stage-1 gate lines

    const int cnt   = g_cnt;
    const int nua   = g_nua;
    const int nfast = g_nfast;
    {
        const ulonglong2* gk = reinterpret_cast<const ulonglong2*>(g_k);
        for (int i = threadIdx.x; i < 7 * cnt; i += TB) s_k[i] = gk[i];
        for (int i = threadIdx.x; i < cnt; i += TB) s_t[i] = g_t[i];
    }
    __syncthreads();

    const int quarter = threadIdx.x >> 6;     // 0..3 (gabor range quarter)
    const int pt      = threadIdx.x & (QTH - 1);
    const int base    = blockIdx.x * PPB;
    const int idx0    = base + pt;
    const int idx1    = base + QTH + pt;

    const float px0 = gx[idx0], px1 = gx[idx1];
    const float py0 = gy[idx0], py1 = gy[idx1];
    const F2 pxP = f2pack(px0, px1);
    const F2 pyP = f2pack(py0, py1);

    const F2 ZERO   = 0ULL;
    const F2 I2PIP  = f2pack(INV2PI_F, INV2PI_F);
    const F2 RC1NP  = f2pack(-RC1, -RC1);
    const F2 RC2NP  = f2pack(-RC2, -RC2);
    const F2 MAGICP = f2pack(MAGIC_F, MAGIC_F);

    F2 acc0 = 0ULL, acc1 = 0ULL, acc2 = 0ULL;

    // ---- class 1: ungated wide gabors — straight-line, no votes/branches ----
    {
        const int n0 = (nua * quarter) >> 2;
        const int n1 = (nua * (quarter + 1)) >> 2;
        const ulonglong2* kn = s_k + 7 * n0;
        for (int n = n0; n < n1; ++n, kn += 7) {
            ulonglong2 q0 = kn[0];
            ulonglong2 q1 = kn[1];
            ulonglong2 q2 = kn[2];
            F2 dx = f2sub(pxP, q0.x);
            F2 dy = f2sub(pyP, q0.y);
            F2 xr = f2fma(dx, q1.x, f2mul(dy, q1.y));
            F2 yr = f2fma(dy, q1.x, f2sub(ZERO, f2mul(dx, q1.y)));
            F2 argL = f2fma(f2mul(yr, yr), q2.y, f2mul(f2mul(xr, xr), q2.x));
            gabor_core(kn, xr, argL, I2PIP, RC1NP, RC2NP, MAGICP, false,
                       acc0, acc1, acc2);
        }
    }

    // ---- class 2: gated thin gabors (fast freq) ----
    {
        const int ng = nfast - nua;
        const int n0 = nua + ((ng * quarter) >> 2);
        const int n1 = nua + ((ng * (quarter + 1)) >> 2);
        const ulonglong2* kn = s_k + 7 * n0;
        const float4* tt = s_t + n0;
        for (int n = n0; n < n1; ++n, kn += 7, ++tt) {
            float4 t = *tt;
            float w0 = fmaf(px0, t.x, fmaf(py0, t.y, t.z));
            float w1 = fmaf(px1, t.x, fmaf(py1, t.y, t.z));
            if (!__any_sync(0xffffffffu, fminf(fabsf(w0), fabsf(w1)) < BTH)) continue;

            ulonglong2 q0 = kn[0];
            ulonglong2 q1 = kn[1];
            ulonglong2 q2 = kn[2];
            F2 dx = f2sub(pxP, q0.x);
            F2 dy = f2sub(pyP, q0.y);
            F2 xr = f2fma(dx, q1.x, f2mul(dy, q1.y));
            F2 yr = f2fma(dy, q1.x, f2sub(ZERO, f2mul(dx, q1.y)));
            F2 argL = f2fma(f2mul(yr, yr), q2.y, f2mul(f2mul(xr, xr), q2.x));

            float a0, a1;
            f2unpack(argL, a0, a1);
            if (!__any_sync(0xffffffffu, fmaxf(a0, a1) > NTHL)) continue;

            gabor_core(kn, xr, argL, I2PIP, RC1NP, RC2NP, MAGICP, false,
                       acc0, acc1, acc2);
        }
    }

    // ---- class 3: slow (extreme-frequency) gabors, gated + fp64 fallback ----
    {
        const int ns = cnt - nfast;
        const int n0 = nfast + ((ns * quarter) >> 2);
        const int n1 = nfast + ((ns * (quarter + 1)) >> 2);
        const ulonglong2* kn = s_k + 7 * n0;
        const float4* tt = s_t + n0;
        for (int n = n0; n < n1; ++n, kn += 7, ++tt) {
            float4 t = *tt;
            float w0 = fmaf(px0, t.x, fmaf(py0, t.y, t.z));
            float w1 = fmaf(px1, t.x, fmaf(py1, t.y, t.z));
            if (!__any_sync(0xffffffffu, fminf(fabsf(w0), fabsf(w1)) < BTH)) continue;

            ulonglong2 q0 = kn[0];
            ulonglong2 q1 = kn[1];
            ulonglong2 q2 = kn[2];
            F2 dx = f2sub(pxP, q0.x);
            F2 dy = f2sub(pyP, q0.y);
            F2 xr = f2fma(dx, q1.x, f2mul(dy, q1.y));
            F2 yr = f2fma(dy, q1.x, f2sub(ZERO, f2mul(dx, q1.y)));
            F2 argL = f2fma(f2mul(yr, yr), q2.y, f2mul(f2mul(xr, xr), q2.x));

            float a0, a1;
            f2unpack(argL, a0, a1);
            if (!__any_sync(0xffffffffu, fmaxf(a0, a1) > NTHL)) continue;

            gabor_core(kn, xr, argL, I2PIP, RC1NP, RC2NP, MAGICP, true,
                       acc0, acc1, acc2);
        }
    }

    // reduction: quarters 1-3 publish partials into the (now dead) param smem
    __syncthreads();
    F2* s_part = reinterpret_cast<F2*>(s_k);
    if (quarter) {
        const int b = (quarter - 1) * 3 * QTH;
        s_part[b + pt]           = acc0;
        s_part[b + QTH + pt]     = acc1;
        s_part[b + 2 * QTH + pt] = acc2;
    }
    __syncthreads();
    if (quarter == 0) {
        #pragma unroll
        for (int qq = 0; qq < 3; ++qq) {
            const int b = qq * 3 * QTH;
            acc0 = f2add(acc0, s_part[b + pt]);
            acc1 = f2add(acc1, s_part[b + QTH + pt]);
            acc2 = f2add(acc2, s_part[b + 2 * QTH + pt]);
        }
        float v0, v1;
        f2unpack(acc0, v0, v1);
        out[idx0] = clampf(v0, -1.f, 1.f);
        out[idx1] = clampf(v1, -1.f, 1.f);
        f2unpack(acc1, v0, v1);
        out[HW + idx0] = clampf(v0, -1.f, 1.f);
        out[HW + idx1] = clampf(v1, -1.f, 1.f);
        f2unpack(acc2, v0, v1);
        out[2 * HW + idx0] = clampf(v0, -1.f, 1.f);
        out[2 * HW + idx1] = clampf(v1, -1.f, 1.f);
    }
}

// ---- launch ----------------------------------------------------------------------
extern "C" void kernel_launch(void* const* d_in, const int* in_sizes, int n_in,
                              void* d_out, int out_size) {
    const float* gx    = (const float*)d_in[0];
    const float* gy    = (const float*)d_in[1];
    const float* u     = (const float*)d_in[2];
    const float* v     = (const float*)d_in[3];
    const float* theta = (const float*)d_in[4];
    const float* rsig  = (const float*)d_in[5];
    const float* rfreq = (const float*)d_in[6];
    const float* gam   = (const float*)d_in[7];
    const float* psi   = (const float*)d_in[8];
    const float* amp   = (const float*)d_in[9];
    float* out = (float*)d_out;

    prep_kernel<<<1, NG>>>(u, v, theta, rsig, rfreq, gam, psi, amp);
    gabor_kernel<<<NBLK, TB>>>(gx, gy, out);
}

// round 11
// speedup vs baseline: 1.9522x; 1.0124x over previous
#include <cuda_runtime.h>
#include <math.h>

#define NG   256
#define HGT  512
#define WID  512
#define HW   (HGT * WID)
#define TB   256
#define QTH  32                // threads per gabor-eighth (one warp)
#define PPB  128               // pixels per block (4 per pixel-thread)
#define NBLK (HW / PPB)        // 2048

// ---- constants -------------------------------------------------------------
constexpr double TWOPI_D  = 6.283185307179586476925286766559;
constexpr float  TWOPI_F  = (float)TWOPI_D;
constexpr float  RC1      = (float)TWOPI_D;
constexpr float  RC2      = (float)(TWOPI_D - (double)RC1);
constexpr float  INV2PI_F = (float)(1.0 / TWOPI_D);
constexpr double INV2PI_D = 1.0 / TWOPI_D;
constexpr float  L2E_F    = 1.4426950408889634f;   // == __expf's log2(e)
constexpr float  MAGIC_F  = 12582912.0f;           // 2^23 + 2^22: rne rounder
constexpr float  BTH      = 5.830951894845301f;    // sqrt(34): axis/width bound
constexpr float  NTHL     = -24.525815695112378f;  // -17 * log2(e)
constexpr float  FR_FAST  = 3.0e6f;  // freq*|xr|max(2.83) < 1e7 -> no fp64 path
constexpr float  W_WIDE   = 0.02f;   // min(sig,gam) >= this -> gate never fires

// ---- packed f32x2 helpers (each half bitwise identical to scalar op) --------
typedef unsigned long long F2;

__device__ __forceinline__ F2 f2pack(float lo, float hi) {
    F2 r; asm("mov.b64 %0, {%1, %2};" : "=l"(r) : "f"(lo), "f"(hi)); return r;
}
__device__ __forceinline__ void f2unpack(F2 v, float& lo, float& hi) {
    asm("mov.b64 {%0, %1}, %2;" : "=f"(lo), "=f"(hi) : "l"(v));
}
__device__ __forceinline__ F2 f2add(F2 a, F2 b) {
    F2 r; asm("add.rn.f32x2 %0, %1, %2;" : "=l"(r) : "l"(a), "l"(b)); return r;
}
__device__ __forceinline__ F2 f2sub(F2 a, F2 b) {
    F2 r; asm("sub.rn.f32x2 %0, %1, %2;" : "=l"(r) : "l"(a), "l"(b)); return r;
}
__device__ __forceinline__ F2 f2mul(F2 a, F2 b) {
    F2 r; asm("mul.rn.f32x2 %0, %1, %2;" : "=l"(r) : "l"(a), "l"(b)); return r;
}
__device__ __forceinline__ F2 f2fma(F2 a, F2 b, F2 c) {
    F2 r; asm("fma.rn.f32x2 %0, %1, %2, %3;" : "=l"(r) : "l"(a), "l"(b), "l"(c)); return r;
}
__device__ __forceinline__ float ex2f(float x) {
    float r; asm("ex2.approx.f32 %0, %1;" : "=f"(r) : "f"(x)); return r;
}
__device__ __forceinline__ float sinaf(float x) {
    float r; asm("sin.approx.f32 %0, %1;" : "=f"(r) : "f"(x)); return r;
}
__device__ __forceinline__ float cosaf(float x) {
    float r; asm("cos.approx.f32 %0, %1;" : "=f"(r) : "f"(x)); return r;
}

// ---- device-global scratch ---------------------------------------------------
// 7 float4 per compacted gabor, every value DUPLICATED into an (x,x) pair:
//   [7n+0]=(uc,uc,vc,vc)  [7n+1]=(cr,cr,sr,sr)    [7n+2]=(i2sL,i2sL,i2gL,i2gL)
//   [7n+3]=(fr,fr,A0,A0)  [7n+4]=(A1,A1,A2,A2)    [7n+5]=(nB0,nB0,nB1,nB1)
//   [7n+6]=(nB2,nB2,0,0)
// i2sL = -log2(e)/(2 sig^2): gaussian = ex2(yr^2*i2gL + xr^2*i2sL).
// g_t[n]=(t0,t1,t2,0): thinnest-axis gate line, |px*t0+py*t1+t2| > sqrt(34)
// == that axis alone drives the gaussian below e^-17.
// Class layout: [0,nUA)=ungated(wide&fast)  [nUA,nFast)=gated thin&fast
//               [nFast,cnt)=slow (fp64 fallback), gated.
__device__ float4 g_k[NG * 7];
__device__ float4 g_t[NG];
__device__ int    g_cnt;
__device__ int    g_nua;
__device__ int    g_nfast;

__device__ __forceinline__ float clampf(float x, float lo, float hi) {
    return fminf(fmaxf(x, lo), hi);
}

// ---- prep kernel: clamp, build coefficients, classify, triple compaction -----
__global__ void prep_kernel(const float* __restrict__ u,
                            const float* __restrict__ v,
                            const float* __restrict__ theta,
                            const float* __restrict__ rsig,
                            const float* __restrict__ rfreq,
                            const float* __restrict__ gam,
                            const float* __restrict__ psi,
                            const float* __restrict__ amp) {
    int n = threadIdx.x;   // 256 threads, 1 block

    float uc = clampf(u[n], -1.f, 1.f);
    float vc = clampf(v[n], -1.f, 1.f);
    float th = clampf(theta[n], -2.f, 2.f) * TWOPI_F;
    float sr, cr;
    sincosf(th, &sr, &cr);

    float sg  = clampf(rsig[n], 1e-5f, 5.f);
    float gm  = clampf(gam[n],  1e-5f, 5.f);
    float i2sL = (-1.f / (2.f * sg * sg)) * L2E_F;
    float i2gL = (-1.f / (2.f * gm * gm)) * L2E_F;
    float fr  = TWOPI_F / expf(rfreq[n]);

    float t0, t1, t2;
    if (sg <= gm) {
        t0 = cr / sg;  t1 = sr / sg;  t2 = -(uc * cr + vc * sr) / sg;
    } else {
        t0 = -sr / gm; t1 = cr / gm;  t2 =  (uc * sr - vc * cr) / gm;
    }

    float A[3], nB[3];
    bool keep = false;
    #pragma unroll
    for (int c = 0; c < 3; ++c) {
        float a  = clampf(amp[3 * n + c], 0.f, 1.f);
        float ph = clampf(psi[3 * n + c], -1.f, 1.f) * TWOPI_F;
        float sp, cp;
        sincosf(ph, &sp, &cp);
        A[c]  =  a * cp;
        nB[c] = -a * sp;
        keep  = keep || (a > 0.f);
    }

    bool fast = fr < FR_FAST;
    bool wide = fminf(sg, gm) >= W_WIDE;

    bool cUA = keep && fast && wide;
    bool cGF = keep && fast && !wide;
    bool cS  = keep && !fast;

    unsigned mA = __ballot_sync(0xffffffffu, cUA);
    unsigned mG = __ballot_sync(0xffffffffu, cGF);
    unsigned mS = __ballot_sync(0xffffffffu, cS);
    __shared__ int wa[8], wg[8], ws[8];
    int wid = n >> 5, lid = n & 31;
    if (lid == 0) { wa[wid] = __popc(mA); wg[wid] = __popc(mG); ws[wid] = __popc(mS); }
    __syncthreads();
    int totA = 0, totG = 0, totS = 0, baseA = 0, baseG = 0, baseS = 0;
    #pragma unroll
    for (int w = 0; w < 8; ++w) {
        if (w < wid) { baseA += wa[w]; baseG += wg[w]; baseS += ws[w]; }
        totA += wa[w]; totG += wg[w]; totS += ws[w];
    }
    if (keep) {
        unsigned lane = (1u << lid) - 1u;
        int p;
        if (cUA)      p = baseA + __popc(mA & lane);
        else if (cGF) p = totA + baseG + __popc(mG & lane);
        else          p = totA + totG + baseS + __popc(mS & lane);
        g_k[7 * p + 0] = make_float4(uc,  uc,  vc,  vc);
        g_k[7 * p + 1] = make_float4(cr,  cr,  sr,  sr);
        g_k[7 * p + 2] = make_float4(i2sL, i2sL, i2gL, i2gL);
        g_k[7 * p + 3] = make_float4(fr,  fr,  A[0], A[0]);
        g_k[7 * p + 4] = make_float4(A[1], A[1], A[2], A[2]);
        g_k[7 * p + 5] = make_float4(nB[0], nB[0], nB[1], nB[1]);
        g_k[7 * p + 6] = make_float4(nB[2], nB[2], 0.f, 0.f);
        g_t[p] = make_float4(t0, t1, t2, 0.f);
    }
    if (n == 0) { g_cnt = totA + totG + totS; g_nua = totA; g_nfast = totA + totG; }
}

// ---- dual-chain active-path body (frozen numerics per half) -------------------
__device__ __forceinline__ void gabor_core2(
    const ulonglong2* kn, F2 xrA, F2 argA, F2 xrB, F2 argB,
    F2 I2PIP, F2 RC1NP, F2 RC2NP, F2 MAGICP, bool FP64,
    F2& a0A, F2& a1A, F2& a2A, F2& a0B, F2& a1B, F2& a2B)
{
    ulonglong2 q3 = kn[3];   // (frP, A0P)
    ulonglong2 q4 = kn[4];   // (A1P, A2P)
    ulonglong2 q5 = kn[5];   // (nB0P, nB1P)
    ulonglong2 q6 = kn[6];   // (nB2P, --)

    // gaussians (amplitude): ex2 of log2-domain args
    float eA0, eA1, eB0, eB1;
    f2unpack(argA, eA0, eA1);
    f2unpack(argB, eB0, eB1);
    float gA0 = ex2f(eA0), gA1 = ex2f(eA1);
    float gB0 = ex2f(eB0), gB1 = ex2f(eB1);

    // carrier phase (frozen): fx = freq*xr; magic-round + 2-term Cody-Waite
    F2 fxA = f2mul(q3.x, xrA);
    F2 fxB = f2mul(q3.x, xrB);
    F2 kA = f2sub(f2fma(fxA, I2PIP, MAGICP), MAGICP);
    F2 kB = f2sub(f2fma(fxB, I2PIP, MAGICP), MAGICP);
    F2 rA = f2fma(kA, RC2NP, f2fma(kA, RC1NP, fxA));
    F2 rB = f2fma(kB, RC2NP, f2fma(kB, RC1NP, fxB));
    float rA0, rA1, rB0, rB1;
    f2unpack(rA, rA0, rA1);
    f2unpack(rB, rB0, rB1);

    if (FP64) {
        float f0, f1;
        f2unpack(fxA, f0, f1);
        if (fabsf(f0) >= 1.0e7f) {
            double xd = (double)f0, q = rint(xd * INV2PI_D);
            rA0 = (float)fma(q, -TWOPI_D, xd);
        }
        if (fabsf(f1) >= 1.0e7f) {
            double xd = (double)f1, q = rint(xd * INV2PI_D);
            rA1 = (float)fma(q, -TWOPI_D, xd);
        }
        f2unpack(fxB, f0, f1);
        if (fabsf(f0) >= 1.0e7f) {
            double xd = (double)f0, q = rint(xd * INV2PI_D);
            rB0 = (float)fma(q, -TWOPI_D, xd);
        }
        if (fabsf(f1) >= 1.0e7f) {
            double xd = (double)f1, q = rint(xd * INV2PI_D);
            rB1 = (float)fma(q, -TWOPI_D, xd);
        }
    }

    float sA0 = sinaf(rA0), cA0 = cosaf(rA0);
    float sA1 = sinaf(rA1), cA1 = cosaf(rA1);
    float sB0 = sinaf(rB0), cB0 = cosaf(rB0);
    float sB1 = sinaf(rB1), cB1 = cosaf(rB1);

    F2 gcA = f2pack(gA0 * cA0, gA1 * cA1);
    F2 gsA = f2pack(gA0 * sA0, gA1 * sA1);
    F2 gcB = f2pack(gB0 * cB0, gB1 * cB1);
    F2 gsB = f2pack(gB0 * sB0, gB1 * sB1);

    a0A = f2fma(gcA, q3.y, f2fma(gsA, q5.x, a0A));
    a1A = f2fma(gcA, q4.x, f2fma(gsA, q5.y, a1A));
    a2A = f2fma(gcA, q4.y, f2fma(gsA, q6.x, a2A));
    a0B = f2fma(gcB, q3.y, f2fma(gsB, q5.x, a0B));
    a1B = f2fma(gcB, q4.x, f2fma(gsB, q5.y, a1B));
    a2B = f2fma(gcB, q4.y, f2fma(gsB, q6.x, a2B));
}

// ---- main kernel: 8-way gabor split (1 warp each), 4 px/thread, 2 f2 chains ---
__global__ void __launch_bounds__(TB)
gabor_kernel(const float* __restrict__ gx,
             const float* __restrict__ gy,
             float* __restrict__ out) {
    __shared__ ulonglong2 s_k[NG * 7];   // 28 KB params; reused for partials
    __shared__ float4     s_t[NG];       // 4 KB stage-1 gate lines

    const int cnt   = g_cnt;
    const int nua   = g_nua;
    const int nfast = g_nfast;
    {
        const ulonglong2* gk = reinterpret_cast<const ulonglong2*>(g_k);
        for (int i = threadIdx.x; i < 7 * cnt; i += TB) s_k[i] = gk[i];
        for (int i = threadIdx.x; i < cnt; i += TB) s_t[i] = g_t[i];
    }
    __syncthreads();

    const int eighth = threadIdx.x >> 5;      // 0..7: warp = gabor-range eighth
    const int pt     = threadIdx.x & (QTH - 1);
    const int base   = blockIdx.x * PPB;
    const int i0 = base + pt,           i1 = base + QTH + pt;
    const int i2 = base + 2 * QTH + pt, i3 = base + 3 * QTH + pt;

    const float pxA0 = gx[i0], pxA1 = gx[i1], pxB0 = gx[i2], pxB1 = gx[i3];
    const float pyA0 = gy[i0], pyA1 = gy[i1], pyB0 = gy[i2], pyB1 = gy[i3];
    const F2 pxA = f2pack(pxA0, pxA1), pyA = f2pack(pyA0, pyA1);
    const F2 pxB = f2pack(pxB0, pxB1), pyB = f2pack(pyB0, pyB1);

    const F2 ZERO   = 0ULL;
    const F2 I2PIP  = f2pack(INV2PI_F, INV2PI_F);
    const F2 RC1NP  = f2pack(-RC1, -RC1);
    const F2 RC2NP  = f2pack(-RC2, -RC2);
    const F2 MAGICP = f2pack(MAGIC_F, MAGIC_F);

    F2 a0A = 0ULL, a1A = 0ULL, a2A = 0ULL;
    F2 a0B = 0ULL, a1B = 0ULL, a2B = 0ULL;

    // ---- class 1: ungated wide gabors — straight-line, no votes/branches ----
    {
        const int n0 = (nua * eighth) >> 3;
        const int n1 = (nua * (eighth + 1)) >> 3;
        const ulonglong2* kn = s_k + 7 * n0;
        for (int n = n0; n < n1; ++n, kn += 7) {
            ulonglong2 q0 = kn[0];
            ulonglong2 q1 = kn[1];
            ulonglong2 q2 = kn[2];
            F2 dxA = f2sub(pxA, q0.x), dyA = f2sub(pyA, q0.y);
            F2 xrA = f2fma(dxA, q1.x, f2mul(dyA, q1.y));
            F2 yrA = f2fma(dyA, q1.x, f2sub(ZERO, f2mul(dxA, q1.y)));
            F2 argA = f2fma(f2mul(yrA, yrA), q2.y, f2mul(f2mul(xrA, xrA), q2.x));
            F2 dxB = f2sub(pxB, q0.x), dyB = f2sub(pyB, q0.y);
            F2 xrB = f2fma(dxB, q1.x, f2mul(dyB, q1.y));
            F2 yrB = f2fma(dyB, q1.x, f2sub(ZERO, f2mul(dxB, q1.y)));
            F2 argB = f2fma(f2mul(yrB, yrB), q2.y, f2mul(f2mul(xrB, xrB), q2.x));
            gabor_core2(kn, xrA, argA, xrB, argB,
                        I2PIP, RC1NP, RC2NP, MAGICP, false,
                        a0A, a1A, a2A, a0B, a1B, a2B);
        }
    }

    // ---- classes 2+3: gated thin gabors (fast, then slow with fp64) ----
    #pragma unroll
    for (int cls = 0; cls < 2; ++cls) {
        const bool fp64 = (cls == 1);
        const int cbase = fp64 ? nfast : nua;
        const int clen  = fp64 ? (cnt - nfast) : (nfast - nua);
        const int n0 = cbase + ((clen * eighth) >> 3);
        const int n1 = cbase + ((clen * (eighth + 1)) >> 3);
        const ulonglong2* kn = s_k + 7 * n0;
        const float4* tt = s_t + n0;
        for (int n = n0; n < n1; ++n, kn += 7, ++tt) {
            float4 t = *tt;
            float wA0 = fmaf(pxA0, t.x, fmaf(pyA0, t.y, t.z));
            float wA1 = fmaf(pxA1, t.x, fmaf(pyA1, t.y, t.z));
            float wB0 = fmaf(pxB0, t.x, fmaf(pyB0, t.y, t.z));
            float wB1 = fmaf(pxB1, t.x, fmaf(pyB1, t.y, t.z));
            float wmin = fminf(fminf(fabsf(wA0), fabsf(wA1)),
                               fminf(fabsf(wB0), fabsf(wB1)));
            if (!__any_sync(0xffffffffu, wmin < BTH)) continue;

            ulonglong2 q0 = kn[0];
            ulonglong2 q1 = kn[1];
            ulonglong2 q2 = kn[2];
            F2 dxA = f2sub(pxA, q0.x), dyA = f2sub(pyA, q0.y);
            F2 xrA = f2fma(dxA, q1.x, f2mul(dyA, q1.y));
            F2 yrA = f2fma(dyA, q1.x, f2sub(ZERO, f2mul(dxA, q1.y)));
            F2 argA = f2fma(f2mul(yrA, yrA), q2.y, f2mul(f2mul(xrA, xrA), q2.x));
            F2 dxB = f2sub(pxB, q0.x), dyB = f2sub(pyB, q0.y);
            F2 xrB = f2fma(dxB, q1.x, f2mul(dyB, q1.y));
            F2 yrB = f2fma(dyB, q1.x, f2sub(ZERO, f2mul(dxB, q1.y)));
            F2 argB = f2fma(f2mul(yrB, yrB), q2.y, f2mul(f2mul(xrB, xrB), q2.x));

            float aA0, aA1, aB0, aB1;
            f2unpack(argA, aA0, aA1);
            f2unpack(argB, aB0, aB1);
            float amax = fmaxf(fmaxf(aA0, aA1), fmaxf(aB0, aB1));
            if (!__any_sync(0xffffffffu, amax > NTHL)) continue;

            gabor_core2(kn, xrA, argA, xrB, argB,
                        I2PIP, RC1NP, RC2NP, MAGICP, fp64,
                        a0A, a1A, a2A, a0B, a1B, a2B);
        }
    }

    // reduction: eighths 1-7 publish 6 partials into the (dead) param smem
    __syncthreads();
    F2* s_part = reinterpret_cast<F2*>(s_k);   // 7 * 6 * 32 F2 = 10.5 KB
    if (eighth) {
        const int b = (eighth - 1) * 6 * QTH + pt;
        s_part[b]           = a0A;
        s_part[b + QTH]     = a1A;
        s_part[b + 2 * QTH] = a2A;
        s_part[b + 3 * QTH] = a0B;
        s_part[b + 4 * QTH] = a1B;
        s_part[b + 5 * QTH] = a2B;
    }
    __syncthreads();
    if (eighth == 0) {
        #pragma unroll
        for (int e = 0; e < 7; ++e) {
            const int b = e * 6 * QTH + pt;
            a0A = f2add(a0A, s_part[b]);
            a1A = f2add(a1A, s_part[b + QTH]);
            a2A = f2add(a2A, s_part[b + 2 * QTH]);
            a0B = f2add(a0B, s_part[b + 3 * QTH]);
            a1B = f2add(a1B, s_part[b + 4 * QTH]);
            a2B = f2add(a2B, s_part[b + 5 * QTH]);
        }
        float v0, v1;
        f2unpack(a0A, v0, v1);
        out[i0] = clampf(v0, -1.f, 1.f);  out[i1] = clampf(v1, -1.f, 1.f);
        f2unpack(a0B, v0, v1);
        out[i2] = clampf(v0, -1.f, 1.f);  out[i3] = clampf(v1, -1.f, 1.f);
        f2unpack(a1A, v0, v1);
        out[HW + i0] = clampf(v0, -1.f, 1.f);  out[HW + i1] = clampf(v1, -1.f, 1.f);
        f2unpack(a1B, v0, v1);
        out[HW + i2] = clampf(v0, -1.f, 1.f);  out[HW + i3] = clampf(v1, -1.f, 1.f);
        f2unpack(a2A, v0, v1);
        out[2 * HW + i0] = clampf(v0, -1.f, 1.f);  out[2 * HW + i1] = clampf(v1, -1.f, 1.f);
        f2unpack(a2B, v0, v1);
        out[2 * HW + i2] = clampf(v0, -1.f, 1.f);  out[2 * HW + i3] = clampf(v1, -1.f, 1.f);
    }
}

// ---- launch ----------------------------------------------------------------------
extern "C" void kernel_launch(void* const* d_in, const int* in_sizes, int n_in,
                              void* d_out, int out_size) {
    const float* gx    = (const float*)d_in[0];
    const float* gy    = (const float*)d_in[1];
    const float* u     = (const float*)d_in[2];
    const float* v     = (const float*)d_in[3];
    const float* theta = (const float*)d_in[4];
    const float* rsig  = (const float*)d_in[5];
    const float* rfreq = (const float*)d_in[6];
    const float* gam   = (const float*)d_in[7];
    const float* psi   = (const float*)d_in[8];
    const float* amp   = (const float*)d_in[9];
    float* out = (float*)d_out;

    prep_kernel<<<1, NG>>>(u, v, theta, rsig, rfreq, gam, psi, amp);
    gabor_kernel<<<NBLK, TB>>>(gx, gy, out);
}